// round 2
// baseline (speedup 1.0000x reference)
#include <cuda_runtime.h>
#include <cuda_bf16.h>

#define BB 4
#define NN 8192
#define CC 1024
#define SS 16
#define NTOK (BB * NN)       // 32768
#define CHUNK 64
#define NCHUNK (NN / CHUNK)  // 128 per batch

typedef unsigned long long ull;

// Scratch: per-token state (pre-cumsum) [token][16], 2 MB -> L2 resident.
__device__ float g_xstate[NTOK * SS];
// Exclusive per-chunk prefixes [b][chunk][16]
__device__ float g_cprefix[BB * NCHUNK * SS];

// ---------- packed f32x2 helpers (sm_103a) ----------
__device__ __forceinline__ ull dup2(float x) {
    ull r;
    unsigned u = __float_as_uint(x);
    asm("mov.b64 %0, {%1, %1};" : "=l"(r) : "r"(u));
    return r;
}
__device__ __forceinline__ void fma2(ull& d, ull a, ull b) {
    asm("fma.rn.f32x2 %0, %1, %2, %0;" : "+l"(d) : "l"(a), "l"(b));
}
__device__ __forceinline__ ull add2(ull a, ull b) {
    ull r;
    asm("add.rn.f32x2 %0, %1, %2;" : "=l"(r) : "l"(a), "l"(b));
    return r;
}

// ================= K1: x_state[t][j] = sum_c x[t][c] * A[c][j] =================
// Block = 256 thr = 8 warps, warp = 4 tokens.
// Lane owns c = 128p + 4l + i  ->  x loads are LDG.128 (one float4/token/phase).
// A is staged swizzled: As[((p*4+i)*8+jp)*32 + l] = A[c][2jp..2jp+1], so the
// inner LDS.64 has 8B lane stride (conflict-free). Prefetch next phase's x.
__global__ void __launch_bounds__(256, 2) k1_xstate(const float* __restrict__ x,
                                                    const float* __restrict__ A) {
    extern __shared__ float2 As[];  // 8192 float2 = 64 KB

    for (int idx = threadIdx.x; idx < CC * 8; idx += 256) {
        int c = idx >> 3, jp = idx & 7;
        int p = c >> 7, l = (c & 127) >> 2, i = c & 3;
        As[(((p * 4 + i) * 8) + jp) * 32 + l] =
            *reinterpret_cast<const float2*>(A + c * SS + jp * 2);
    }
    __syncthreads();

    const int w = threadIdx.x >> 5;
    const int l = threadIdx.x & 31;
    const long t0 = (long)blockIdx.x * 32 + w * 4;
    const float* xp = x + t0 * CC + 4 * l;

    ull acc[32];
#pragma unroll
    for (int v = 0; v < 32; v++) acc[v] = 0ull;

    float4 cur[4], nxt[4];
#pragma unroll
    for (int t = 0; t < 4; t++)
        cur[t] = *reinterpret_cast<const float4*>(xp + t * CC);

#pragma unroll
    for (int p = 0; p < 8; p++) {
        if (p < 7) {
#pragma unroll
            for (int t = 0; t < 4; t++)
                nxt[t] = *reinterpret_cast<const float4*>(xp + t * CC + (p + 1) * 128);
        }
        const float2* Ap = As + (p * 4) * 8 * 32 + l;
#pragma unroll
        for (int i = 0; i < 4; i++) {
            ull xd[4];
            xd[0] = dup2(i == 0 ? cur[0].x : i == 1 ? cur[0].y : i == 2 ? cur[0].z : cur[0].w);
            xd[1] = dup2(i == 0 ? cur[1].x : i == 1 ? cur[1].y : i == 2 ? cur[1].z : cur[1].w);
            xd[2] = dup2(i == 0 ? cur[2].x : i == 1 ? cur[2].y : i == 2 ? cur[2].z : cur[2].w);
            xd[3] = dup2(i == 0 ? cur[3].x : i == 1 ? cur[3].y : i == 2 ? cur[3].z : cur[3].w);
#pragma unroll
            for (int jp = 0; jp < 8; jp++) {
                ull a2 = *reinterpret_cast<const ull*>(Ap + (i * 8 + jp) * 32);
#pragma unroll
                for (int t = 0; t < 4; t++) fma2(acc[t * 8 + jp], xd[t], a2);
            }
        }
#pragma unroll
        for (int t = 0; t < 4; t++) cur[t] = nxt[t];
    }

    // Folding transpose-reduce: 32 values across 32 lanes -> lane l holds full
    // sum of value index l (index = t*8 + jp).
#pragma unroll
    for (int ofs = 16; ofs; ofs >>= 1) {
        const bool hi = (l & ofs) != 0;
#pragma unroll
        for (int k = 0; k < 32; k++) {
            if (k >= ofs) continue;  // compile-time pruned
            ull send = hi ? acc[k] : acc[k + ofs];
            ull recv = __shfl_xor_sync(0xffffffffu, send, ofs);
            ull keep = hi ? acc[k + ofs] : acc[k];
            acc[k] = add2(keep, recv);
        }
    }

    // lane l: t = l>>3, jp = l&7  -> contiguous 256B warp store
    *reinterpret_cast<ull*>(&g_xstate[(t0 + (l >> 3)) * SS + (l & 7) * 2]) = acc[0];
}

// ================= K2: exclusive scan of chunk sums =================
// Grid = BB*4 blocks (4 j-groups of 4); 128 threads = one per chunk.
__global__ void __launch_bounds__(128) k2_scan() {
    const int b = blockIdx.x >> 2;
    const int jg = blockIdx.x & 3;
    const int ch = threadIdx.x;  // 0..127

    const float4* p = reinterpret_cast<const float4*>(
        g_xstate + ((long)b * NN + (long)ch * CHUNK) * SS + jg * 4);
    float4 s = make_float4(0.f, 0.f, 0.f, 0.f);
#pragma unroll 8
    for (int i = 0; i < CHUNK; i++) {
        float4 v = p[i * 4];
        s.x += v.x; s.y += v.y; s.z += v.z; s.w += v.w;
    }

    __shared__ float4 sc[NCHUNK];
    sc[ch] = s;
    __syncthreads();
    float4 v = s;
    for (int o = 1; o < NCHUNK; o <<= 1) {
        float4 u = (ch >= o) ? sc[ch - o] : make_float4(0.f, 0.f, 0.f, 0.f);
        __syncthreads();
        v.x += u.x; v.y += u.y; v.z += u.z; v.w += u.w;
        sc[ch] = v;
        __syncthreads();
    }
    float4 e = make_float4(v.x - s.x, v.y - s.y, v.z - s.z, v.w - s.w);
    *reinterpret_cast<float4*>(
        &g_cprefix[((long)b * NCHUNK + ch) * SS + jg * 4]) = e;
}

// ================= K3: local cumsum + (cumstate @ D) =================
// Grid = B*NCHUNK = 512 blocks of 256 thr. Block = one 64-token chunk.
__global__ void __launch_bounds__(256, 2) k3_out(const float* __restrict__ Dg,
                                                 float* __restrict__ out) {
    __shared__ float2 cs2[CHUNK][SS + 2];  // duplicated cumstate; 144B rows (16B-aligned)

    const int b = blockIdx.x >> 7;
    const int ch = blockIdx.x & 127;
    const long T0 = (long)b * NN + (long)ch * CHUNK;
    const int w = threadIdx.x >> 5;
    const int l = threadIdx.x & 31;

    // Warp w computes the cumsum for j = 2w, 2w+1 via warp scans.
#pragma unroll
    for (int jj = 0; jj < 2; jj++) {
        const int j = w * 2 + jj;
        const float pfx = g_cprefix[((long)b * NCHUNK + ch) * SS + j];
        float v0 = g_xstate[(T0 + l) * SS + j];
        float v1 = g_xstate[(T0 + 32 + l) * SS + j];
#pragma unroll
        for (int o = 1; o < 32; o <<= 1) {
            float u = __shfl_up_sync(0xffffffffu, v0, o);
            if (l >= o) v0 += u;
        }
        const float carry = __shfl_sync(0xffffffffu, v0, 31);
#pragma unroll
        for (int o = 1; o < 32; o <<= 1) {
            float u = __shfl_up_sync(0xffffffffu, v1, o);
            if (l >= o) v1 += u;
        }
        v0 += pfx;
        v1 += pfx + carry;
        cs2[l][j] = make_float2(v0, v0);
        cs2[32 + l][j] = make_float2(v1, v1);
    }
    __syncthreads();

    // D fragment in registers: lane owns c = w*128 + 4*l + {0..3}
    const int cbase = w * 128 + l * 4;
    ull dfrag[SS][2];
#pragma unroll
    for (int j = 0; j < SS; j++) {
#pragma unroll
        for (int s = 0; s < 2; s++)
            dfrag[j][s] = *reinterpret_cast<const ull*>(Dg + j * CC + cbase + 2 * s);
    }

    float* op = out + T0 * CC + cbase;
#pragma unroll
    for (int tg = 0; tg < 16; tg++) {
#pragma unroll
        for (int t = 0; t < 4; t++) {
            const int tt = tg * 4 + t;
            const float4* row = reinterpret_cast<const float4*>(&cs2[tt][0]);
            ull o0 = 0ull, o1 = 0ull;
#pragma unroll
            for (int q = 0; q < 8; q++) {
                union { float4 f; ull u[2]; } cc;
                cc.f = row[q];  // {cs[2q],cs[2q],cs[2q+1],cs[2q+1]}
                fma2(o0, cc.u[0], dfrag[2 * q][0]);
                fma2(o1, cc.u[0], dfrag[2 * q][1]);
                fma2(o0, cc.u[1], dfrag[2 * q + 1][0]);
                fma2(o1, cc.u[1], dfrag[2 * q + 1][1]);
            }
            union { ull u[2]; float4 f; } r;
            r.u[0] = o0;
            r.u[1] = o1;
            *reinterpret_cast<float4*>(op + (long)tt * CC) = r.f;  // STG.128
        }
    }
}

extern "C" void kernel_launch(void* const* d_in, const int* in_sizes, int n_in,
                              void* d_out, int out_size) {
    const float* x = (const float*)d_in[0];
    const float* A = (const float*)d_in[1];
    const float* D = (const float*)d_in[2];
    float* out = (float*)d_out;

    cudaFuncSetAttribute(k1_xstate, cudaFuncAttributeMaxDynamicSharedMemorySize,
                         8 * CC * (int)sizeof(float2));

    k1_xstate<<<NTOK / 32, 256, 8 * CC * sizeof(float2)>>>(x, A);
    k2_scan<<<BB * 4, NCHUNK>>>();
    k3_out<<<BB * NCHUNK, 256>>>(D, out);
}

// round 3
// speedup vs baseline: 1.3338x; 1.3338x over previous
#include <cuda_runtime.h>
#include <cuda_bf16.h>

#define BB 4
#define NN 8192
#define CC 1024
#define SS 16
#define NTOK (BB * NN)       // 32768
#define CHUNK 64
#define NCHUNK (NN / CHUNK)  // 128 per batch

typedef unsigned long long ull;

// Scratch: per-token state (pre-cumsum) [token][16], 2 MB -> L2 resident.
__device__ float g_xstate[NTOK * SS];
// Exclusive per-chunk prefixes [b][chunk][16]
__device__ float g_cprefix[BB * NCHUNK * SS];

// ---------- packed f32x2 + async helpers ----------
__device__ __forceinline__ ull dup2(float x) {
    ull r;
    unsigned u = __float_as_uint(x);
    asm("mov.b64 %0, {%1, %1};" : "=l"(r) : "r"(u));
    return r;
}
__device__ __forceinline__ void fma2(ull& d, ull a, ull b) {
    asm("fma.rn.f32x2 %0, %1, %2, %0;" : "+l"(d) : "l"(a), "l"(b));
}
__device__ __forceinline__ unsigned sptr(const void* p) {
    unsigned r;
    asm("{.reg .u64 t; cvta.to.shared.u64 t, %1; cvt.u32.u64 %0, t;}"
        : "=r"(r) : "l"(p));
    return r;
}
__device__ __forceinline__ void cp16(unsigned d, const void* s) {
    asm volatile("cp.async.ca.shared.global [%0], [%1], 16;" :: "r"(d), "l"(s));
}
__device__ __forceinline__ void cp8(unsigned d, const void* s) {
    asm volatile("cp.async.ca.shared.global [%0], [%1], 8;" :: "r"(d), "l"(s));
}
__device__ __forceinline__ void cp_commit() {
    asm volatile("cp.async.commit_group;");
}

// ================= K1: x_state[t][j] = sum_c x[t][c] * A[c][j] =================
// Block = 128 thr; thread = one token (lane = token within warp).
// x staged in smem transposed tiles [128 t][32 c] via cp.async (double buffered,
// XOR-swizzled so LDS.128 per-lane-token reads are conflict-free).
// A chunk staged as ull pairs A_s[jp][c]; inner reads are LDS.128 BROADCAST
// (1 crossbar cycle) -> fma pipe is the binding resource.
__global__ void __launch_bounds__(128) k1_xstate(const float* __restrict__ x,
                                                 const float* __restrict__ A) {
    __shared__ float xs[2][128 * 32];  // 2 x 16 KB
    __shared__ ull As[2][8 * 32];      // 2 x 2 KB  [jp][c]

    const int tid = threadIdx.x;
    const long T0 = (long)blockIdx.x * 128;

    auto issue = [&](int ch, int buf) {
        const int c0 = ch * 32;
#pragma unroll
        for (int i = 0; i < 8; i++) {
            int lin = tid + i * 128;
            int t = lin >> 3, cq = lin & 7;
            unsigned dst = sptr(&xs[buf][t * 32 + ((cq ^ (t & 7)) << 2)]);
            cp16(dst, x + (T0 + t) * CC + c0 + cq * 4);
        }
#pragma unroll
        for (int i = 0; i < 2; i++) {
            int lin = tid + i * 128;
            int jp = lin >> 5, c = lin & 31;
            unsigned dst = sptr(&As[buf][jp * 32 + c]);
            cp8(dst, A + (c0 + c) * SS + jp * 2);
        }
        cp_commit();
    };

    issue(0, 0);
    issue(1, 1);

    ull acc[8];
#pragma unroll
    for (int jp = 0; jp < 8; jp++) acc[jp] = 0ull;

    const int t = tid;  // local token
    const int tsw = t & 7;

    for (int ch = 0; ch < 32; ch++) {
        const int buf = ch & 1;
        if (ch < 30)
            asm volatile("cp.async.wait_group 1;");
        else
            asm volatile("cp.async.wait_group 0;");
        __syncthreads();

        const float* xrow = &xs[buf][t * 32];
        const ull* Ab = &As[buf][0];
#pragma unroll
        for (int cq = 0; cq < 8; cq++) {
            float4 xv = *reinterpret_cast<const float4*>(&xrow[(cq ^ tsw) << 2]);
            ull xd0 = dup2(xv.x), xd1 = dup2(xv.y), xd2 = dup2(xv.z),
                xd3 = dup2(xv.w);
#pragma unroll
            for (int jp = 0; jp < 8; jp++) {
                ulonglong2 p0 = *reinterpret_cast<const ulonglong2*>(
                    &Ab[jp * 32 + cq * 4]);       // broadcast LDS.128
                ulonglong2 p1 = *reinterpret_cast<const ulonglong2*>(
                    &Ab[jp * 32 + cq * 4 + 2]);   // broadcast LDS.128
                fma2(acc[jp], xd0, p0.x);
                fma2(acc[jp], xd1, p0.y);
                fma2(acc[jp], xd2, p1.x);
                fma2(acc[jp], xd3, p1.y);
            }
        }
        __syncthreads();
        if (ch + 2 < 32) issue(ch + 2, buf);
    }

    // Store: thread writes its token's 16 states = 4 x STG.128, warp-coalesced.
    float* dst = &g_xstate[(T0 + t) * SS];
#pragma unroll
    for (int q = 0; q < 4; q++) {
        ulonglong2 v;
        v.x = acc[2 * q];
        v.y = acc[2 * q + 1];
        *reinterpret_cast<ulonglong2*>(dst + q * 4) = v;
    }
}

// ================= K2: exclusive scan of chunk sums =================
// Grid = BB*4 (b, j-group of 4); block 512: 4 threads cooperate per chunk.
__global__ void __launch_bounds__(512) k2_scan() {
    const int b = blockIdx.x >> 2;
    const int jg = blockIdx.x & 3;
    const int tid = threadIdx.x;
    const int ch = tid >> 2, sub = tid & 3;

    __shared__ float4 part[512];
    __shared__ float4 sc[NCHUNK];

    const float4* p = reinterpret_cast<const float4*>(
        g_xstate + ((long)b * NN + (long)ch * CHUNK + sub * 16) * SS + jg * 4);
    float4 s = make_float4(0.f, 0.f, 0.f, 0.f);
#pragma unroll
    for (int i = 0; i < 16; i++) {
        float4 v = p[i * 4];
        s.x += v.x; s.y += v.y; s.z += v.z; s.w += v.w;
    }
    part[tid] = s;
    __syncthreads();

    float4 tot = make_float4(0.f, 0.f, 0.f, 0.f);
    float4 v = tot;
    if (tid < NCHUNK) {
#pragma unroll
        for (int k = 0; k < 4; k++) {
            float4 u = part[tid * 4 + k];
            tot.x += u.x; tot.y += u.y; tot.z += u.z; tot.w += u.w;
        }
        sc[tid] = tot;
        v = tot;
    }
    for (int o = 1; o < NCHUNK; o <<= 1) {
        __syncthreads();
        float4 u = make_float4(0.f, 0.f, 0.f, 0.f);
        if (tid < NCHUNK && tid >= o) u = sc[tid - o];
        __syncthreads();
        if (tid < NCHUNK) {
            v.x += u.x; v.y += u.y; v.z += u.z; v.w += u.w;
            sc[tid] = v;
        }
    }
    if (tid < NCHUNK) {
        float4 e = make_float4(v.x - tot.x, v.y - tot.y, v.z - tot.z, v.w - tot.w);
        *reinterpret_cast<float4*>(
            &g_cprefix[((long)b * NCHUNK + tid) * SS + jg * 4]) = e;
    }
}

// ================= K3: local cumsum + (cumstate @ D) =================
// Grid = 512 blocks (one 64-token chunk) of 512 thr; thread owns 2 channels.
// D fragment: 16 ull = 32 regs; cumstate read via broadcast LDS.128.
__global__ void __launch_bounds__(512) k3_out(const float* __restrict__ Dg,
                                              float* __restrict__ out) {
    __shared__ ull cs_s[CHUNK][SS + 2];  // duplicated pairs; 144B rows (16B-aligned)

    const int tid = threadIdx.x;
    const int b = blockIdx.x >> 7;
    const int ch = blockIdx.x & 127;
    const long T0 = (long)b * NN + (long)ch * CHUNK;
    const int w = tid >> 5;
    const int l = tid & 31;

    // Warp w computes the cumsum for j = w (16 warps cover 16 states).
    {
        const int j = w;
        const float pfx = g_cprefix[((long)b * NCHUNK + ch) * SS + j];
        float v0 = g_xstate[(T0 + l) * SS + j];
        float v1 = g_xstate[(T0 + 32 + l) * SS + j];
#pragma unroll
        for (int o = 1; o < 32; o <<= 1) {
            float u = __shfl_up_sync(0xffffffffu, v0, o);
            if (l >= o) v0 += u;
        }
        const float carry = __shfl_sync(0xffffffffu, v0, 31);
#pragma unroll
        for (int o = 1; o < 32; o <<= 1) {
            float u = __shfl_up_sync(0xffffffffu, v1, o);
            if (l >= o) v1 += u;
        }
        cs_s[l][j] = dup2(v0 + pfx);
        cs_s[32 + l][j] = dup2(v1 + pfx + carry);
    }
    __syncthreads();

    // D fragment: thread owns c = 2*tid, 2*tid+1
    const int cbase = tid * 2;
    ull dfrag[SS];
#pragma unroll
    for (int j = 0; j < SS; j++)
        dfrag[j] = *reinterpret_cast<const ull*>(Dg + j * CC + cbase);

    float* op = out + T0 * CC + cbase;
#pragma unroll 4
    for (int tt = 0; tt < CHUNK; tt++) {
        ull oa = 0ull, ob = 0ull;  // dual accumulators (break dep chain)
#pragma unroll
        for (int q = 0; q < 8; q++) {
            ulonglong2 c2 =
                *reinterpret_cast<const ulonglong2*>(&cs_s[tt][q * 2]);  // bcast
            fma2(oa, c2.x, dfrag[2 * q]);
            fma2(ob, c2.y, dfrag[2 * q + 1]);
        }
        asm("add.rn.f32x2 %0, %0, %1;" : "+l"(oa) : "l"(ob));
        *reinterpret_cast<ull*>(op + (long)tt * CC) = oa;  // STG.64 coalesced
    }
}

extern "C" void kernel_launch(void* const* d_in, const int* in_sizes, int n_in,
                              void* d_out, int out_size) {
    const float* x = (const float*)d_in[0];
    const float* A = (const float*)d_in[1];
    const float* D = (const float*)d_in[2];
    float* out = (float*)d_out;

    k1_xstate<<<NTOK / 128, 128>>>(x, A);
    k2_scan<<<BB * 4, 512>>>();
    k3_out<<<BB * NCHUNK, 512>>>(D, out);
}

// round 5
// speedup vs baseline: 1.7765x; 1.3320x over previous
#include <cuda_runtime.h>
#include <cuda_bf16.h>

#define BB 4
#define NN 8192
#define CC 1024
#define SS 16
#define NTOK (BB * NN)       // 32768
#define CHUNK 64
#define NCHUNK (NN / CHUNK)  // 128 per batch
#define NCHUNKS_TOT (BB * NCHUNK)  // 512

typedef unsigned long long ull;

// Per-token state (pre-cumsum) [token][16], 2 MB -> L2 resident.
__device__ float g_xstate[NTOK * SS];
// Per-chunk raw sums [chunk][16] (written by K1)
__device__ float g_chsum[NCHUNKS_TOT * SS];
// Exclusive per-chunk prefixes [b][chunk][16]
__device__ float g_cprefix[NCHUNKS_TOT * SS];

// ---------- packed f32x2 + async helpers ----------
__device__ __forceinline__ ull dup2(float x) {
    ull r;
    unsigned u = __float_as_uint(x);
    asm("mov.b64 %0, {%1, %1};" : "=l"(r) : "r"(u));
    return r;
}
__device__ __forceinline__ void fma2(ull& d, ull a, ull b) {
    asm("fma.rn.f32x2 %0, %1, %2, %0;" : "+l"(d) : "l"(a), "l"(b));
}
__device__ __forceinline__ ull add2(ull a, ull b) {
    ull r;
    asm("add.rn.f32x2 %0, %1, %2;" : "=l"(r) : "l"(a), "l"(b));
    return r;
}
__device__ __forceinline__ unsigned sptr(const void* p) {
    unsigned r;
    asm("{.reg .u64 t; cvta.to.shared.u64 t, %1; cvt.u32.u64 %0, t;}"
        : "=r"(r) : "l"(p));
    return r;
}
__device__ __forceinline__ void cp16(unsigned d, const void* s) {
    asm volatile("cp.async.ca.shared.global [%0], [%1], 16;" :: "r"(d), "l"(s));
}
__device__ __forceinline__ void cp_commit() {
    asm volatile("cp.async.commit_group;");
}

// ================= K1: x_state + chunk sums =================
// Block = 256 thr = 8 warps = one 64-token chunk.
// Warp w owns the c-subrange [it*64 + w*8, +8) each iteration (8-way C split,
// interleaved so each iter's block footprint is a contiguous 64-c window).
// Lane handles tokens (l) and (32+l): A registers reused for 2 tokens ->
// A-LDS : fma2 ratio = 1 : 4.
// x rows in smem padded to 272B (68 words; 68 % 32 == 4 -> LDS.128 4-phase
// conflict-free). cp.async double-buffered, fully coalesced (nL<=4).
#define XSROW 68  // words per token row (64 data + 4 pad)

__global__ void __launch_bounds__(256) k1_xstate(const float* __restrict__ x,
                                                 const float* __restrict__ A) {
    __shared__ __align__(16) float xs[2][64 * XSROW];  // 34.8 KB
    __shared__ __align__(16) ull As[2][64 * 8];        // 8 KB  [c][jp]
    __shared__ ull csum_s[8][2];

    const int tid = threadIdx.x;
    const int w = tid >> 5;   // = eighth
    const int l = tid & 31;
    const long T0 = (long)blockIdx.x * 64;

    auto issue = [&](int it, int buf) {
        const float* xbase = x + T0 * CC + it * 64;
#pragma unroll
        for (int j = 0; j < 4; j++) {
            int o = tid + j * 256;
            int t = o >> 4, sub = o & 15;
            cp16(sptr(&xs[buf][t * XSROW + sub * 4]), xbase + (long)t * CC + sub * 4);
        }
        {
            int c = tid >> 2, k = tid & 3;
            cp16(sptr(&As[buf][c * 8 + k * 2]), A + (it * 64 + c) * SS + k * 4);
        }
        cp_commit();
    };

    issue(0, 0);
    issue(1, 1);

    ull acc[2][8];
#pragma unroll
    for (int t = 0; t < 2; t++)
#pragma unroll
        for (int jp = 0; jp < 8; jp++) acc[t][jp] = 0ull;

    for (int it = 0; it < 16; it++) {
        const int buf = it & 1;
        if (it < 15)
            asm volatile("cp.async.wait_group 1;");
        else
            asm volatile("cp.async.wait_group 0;");
        __syncthreads();

        const float* xa = &xs[buf][l * XSROW + w * 8];
        const float* xb = &xs[buf][(32 + l) * XSROW + w * 8];
        const ull* Arow = &As[buf][w * 8 * 8];

#pragma unroll
        for (int cc = 0; cc < 2; cc++) {
            float4 va = *reinterpret_cast<const float4*>(xa + cc * 4);
            float4 vb = *reinterpret_cast<const float4*>(xb + cc * 4);
            float fa[4] = {va.x, va.y, va.z, va.w};
            float fb[4] = {vb.x, vb.y, vb.z, vb.w};
#pragma unroll
            for (int k = 0; k < 4; k++) {
                const int c = cc * 4 + k;
                ull xda = dup2(fa[k]);
                ull xdb = dup2(fb[k]);
#pragma unroll
                for (int jq = 0; jq < 4; jq++) {
                    ulonglong2 a2 = *reinterpret_cast<const ulonglong2*>(
                        Arow + c * 8 + jq * 2);
                    fma2(acc[0][jq * 2], xda, a2.x);
                    fma2(acc[0][jq * 2 + 1], xda, a2.y);
                    fma2(acc[1][jq * 2], xdb, a2.x);
                    fma2(acc[1][jq * 2 + 1], xdb, a2.y);
                }
            }
        }
        __syncthreads();
        if (it + 2 < 16) issue(it + 2, buf);
    }

    // ---- cross-eighth reduce (alias xs as red[8 e][64 t][8 jp] ull) ----
    __syncthreads();
    ull* red = reinterpret_cast<ull*>(&xs[0][0]);
#pragma unroll
    for (int jp = 0; jp < 8; jp++) {
        red[((w * 64) + l) * 8 + jp] = acc[0][jp];
        red[((w * 64) + 32 + l) * 8 + jp] = acc[1][jp];
    }
    __syncthreads();

    // thread (jj = tid>>6 in 0..3, t = tid&63): states 4jj..4jj+3
    const int jj = tid >> 6;
    const int t = tid & 63;
    ull s0 = 0ull, s1 = 0ull;
#pragma unroll
    for (int e = 0; e < 8; e++) {
        ulonglong2 v = *reinterpret_cast<const ulonglong2*>(
            &red[(e * 64 + t) * 8 + jj * 2]);
        s0 = add2(s0, v.x);
        s1 = add2(s1, v.y);
    }
    {
        ulonglong2 v;
        v.x = s0;
        v.y = s1;
        *reinterpret_cast<ulonglong2*>(&g_xstate[(T0 + t) * SS + jj * 4]) = v;
    }

    // chunk sum over the 64 tokens (warps 2jj, 2jj+1 hold them)
#pragma unroll
    for (int o = 16; o; o >>= 1) {
        s0 = add2(s0, __shfl_xor_sync(0xffffffffu, s0, o));
        s1 = add2(s1, __shfl_xor_sync(0xffffffffu, s1, o));
    }
    if (l == 0) {
        csum_s[w][0] = s0;
        csum_s[w][1] = s1;
    }
    __syncthreads();
    if (tid < 4) {
        ulonglong2 v;
        v.x = add2(csum_s[2 * tid][0], csum_s[2 * tid + 1][0]);
        v.y = add2(csum_s[2 * tid][1], csum_s[2 * tid + 1][1]);
        *reinterpret_cast<ulonglong2*>(&g_chsum[blockIdx.x * SS + tid * 4]) = v;
    }
}

// ================= K2: exclusive scan of chunk sums (8K floats) =================
// Grid = 16 blocks (b x jgroup); 128 threads = one per chunk.
__global__ void __launch_bounds__(128) k2_scan() {
    const int b = blockIdx.x >> 2;
    const int jg = blockIdx.x & 3;
    const int ch = threadIdx.x;

    float4 s = *reinterpret_cast<const float4*>(
        &g_chsum[((long)b * NCHUNK + ch) * SS + jg * 4]);
    __shared__ float4 sc[NCHUNK];
    sc[ch] = s;
    __syncthreads();
    float4 v = s;
    for (int o = 1; o < NCHUNK; o <<= 1) {
        float4 u = (ch >= o) ? sc[ch - o] : make_float4(0.f, 0.f, 0.f, 0.f);
        __syncthreads();
        v.x += u.x; v.y += u.y; v.z += u.z; v.w += u.w;
        sc[ch] = v;
        __syncthreads();
    }
    float4 e = make_float4(v.x - s.x, v.y - s.y, v.z - s.z, v.w - s.w);
    *reinterpret_cast<float4*>(
        &g_cprefix[((long)b * NCHUNK + ch) * SS + jg * 4]) = e;
}

// ================= K3: local cumsum + (cumstate @ D) =================
// Grid = 512 blocks (one 64-token chunk) of 512 thr; thread owns 2 channels.
__global__ void __launch_bounds__(512) k3_out(const float* __restrict__ Dg,
                                              float* __restrict__ out) {
    __shared__ ull cs_s[CHUNK][SS + 2];  // duplicated pairs; 144B rows

    const int tid = threadIdx.x;
    const int b = blockIdx.x >> 7;
    const int ch = blockIdx.x & 127;
    const long T0 = (long)b * NN + (long)ch * CHUNK;
    const int w = tid >> 5;
    const int l = tid & 31;

    // Warp w computes the cumsum for state j = w.
    {
        const int j = w;
        const float pfx = g_cprefix[((long)b * NCHUNK + ch) * SS + j];
        float v0 = g_xstate[(T0 + l) * SS + j];
        float v1 = g_xstate[(T0 + 32 + l) * SS + j];
#pragma unroll
        for (int o = 1; o < 32; o <<= 1) {
            float u = __shfl_up_sync(0xffffffffu, v0, o);
            if (l >= o) v0 += u;
        }
        const float carry = __shfl_sync(0xffffffffu, v0, 31);
#pragma unroll
        for (int o = 1; o < 32; o <<= 1) {
            float u = __shfl_up_sync(0xffffffffu, v1, o);
            if (l >= o) v1 += u;
        }
        cs_s[l][j] = dup2(v0 + pfx);
        cs_s[32 + l][j] = dup2(v1 + pfx + carry);
    }
    __syncthreads();

    // D fragment: thread owns c = 2*tid, 2*tid+1
    const int cbase = tid * 2;
    ull dfrag[SS];
#pragma unroll
    for (int j = 0; j < SS; j++)
        dfrag[j] = *reinterpret_cast<const ull*>(Dg + j * CC + cbase);

    float* op = out + T0 * CC + cbase;
#pragma unroll 4
    for (int tt = 0; tt < CHUNK; tt++) {
        ull oa = 0ull, ob = 0ull;
#pragma unroll
        for (int q = 0; q < 8; q++) {
            ulonglong2 c2 =
                *reinterpret_cast<const ulonglong2*>(&cs_s[tt][q * 2]);  // bcast
            fma2(oa, c2.x, dfrag[2 * q]);
            fma2(ob, c2.y, dfrag[2 * q + 1]);
        }
        asm("add.rn.f32x2 %0, %0, %1;" : "+l"(oa) : "l"(ob));
        *reinterpret_cast<ull*>(op + (long)tt * CC) = oa;
    }
}

extern "C" void kernel_launch(void* const* d_in, const int* in_sizes, int n_in,
                              void* d_out, int out_size) {
    const float* x = (const float*)d_in[0];
    const float* A = (const float*)d_in[1];
    const float* D = (const float*)d_in[2];
    float* out = (float*)d_out;

    k1_xstate<<<NCHUNKS_TOT, 256>>>(x, A);
    k2_scan<<<16, 128>>>();
    k3_out<<<NCHUNKS_TOT, 512>>>(D, out);
}

// round 6
// speedup vs baseline: 1.8936x; 1.0659x over previous
#include <cuda_runtime.h>
#include <cuda_bf16.h>

#define BB 4
#define NN 8192
#define CC 1024
#define SS 16
#define NTOK (BB * NN)             // 32768
#define CHUNK 64
#define NCHUNK (NN / CHUNK)        // 128 per batch
#define NCHUNKS_TOT (BB * NCHUNK)  // 512

typedef unsigned long long ull;

// Partial per-token state (pre-cumsum), one per c-half: 2 x 2 MB (L2-resident)
__device__ float g_xstate[2][NTOK * SS];
// Partial per-chunk raw sums per c-half
__device__ float g_chsum[2][NCHUNKS_TOT * SS];
// Exclusive per-chunk prefixes (combined)
__device__ float g_cprefix[NCHUNKS_TOT * SS];

// ---------- packed f32x2 + async helpers ----------
__device__ __forceinline__ ull dup2(float x) {
    ull r;
    unsigned u = __float_as_uint(x);
    asm("mov.b64 %0, {%1, %1};" : "=l"(r) : "r"(u));
    return r;
}
__device__ __forceinline__ void fma2(ull& d, ull a, ull b) {
    asm("fma.rn.f32x2 %0, %1, %2, %0;" : "+l"(d) : "l"(a), "l"(b));
}
__device__ __forceinline__ ull add2(ull a, ull b) {
    ull r;
    asm("add.rn.f32x2 %0, %1, %2;" : "=l"(r) : "l"(a), "l"(b));
    return r;
}
__device__ __forceinline__ unsigned sptr(const void* p) {
    unsigned r;
    asm("{.reg .u64 t; cvta.to.shared.u64 t, %1; cvt.u32.u64 %0, t;}"
        : "=r"(r) : "l"(p));
    return r;
}
__device__ __forceinline__ void cp16(unsigned d, const void* s) {
    asm volatile("cp.async.ca.shared.global [%0], [%1], 16;" :: "r"(d), "l"(s));
}
__device__ __forceinline__ void cp_commit() {
    asm volatile("cp.async.commit_group;");
}

// ================= K1: partial x_state + chunk sums =================
// Grid = 1024: block = (64-token chunk) x (512-c half). 256 thr = 8 warps.
// Per 64-c window iter: warp w owns 8 c's; lane handles tokens l and 32+l
// (A registers reused across 2 tokens -> A-LDS : fma2 = 1 : 4).
// x rows padded to 272B (68 words; 68 % 32 == 4 -> LDS.128 conflict-free).
#define XSROW 68

__global__ void __launch_bounds__(256) k1_xstate(const float* __restrict__ x,
                                                 const float* __restrict__ A) {
    __shared__ __align__(16) float xs[2][64 * XSROW];  // 34.8 KB
    __shared__ __align__(16) ull As[2][64 * 8];        // 8 KB  [c][jp]
    __shared__ ull csum_s[8][2];

    const int tid = threadIdx.x;
    const int w = tid >> 5;
    const int l = tid & 31;
    const int chunk = blockIdx.x >> 1;
    const int half = blockIdx.x & 1;
    const long T0 = (long)chunk * 64;
    const int C0 = half * 512;

    auto issue = [&](int it, int buf) {
        const float* xbase = x + T0 * CC + C0 + it * 64;
#pragma unroll
        for (int j = 0; j < 4; j++) {
            int o = tid + j * 256;
            int t = o >> 4, sub = o & 15;
            cp16(sptr(&xs[buf][t * XSROW + sub * 4]),
                 xbase + (long)t * CC + sub * 4);
        }
        {
            int c = tid >> 2, k = tid & 3;
            cp16(sptr(&As[buf][c * 8 + k * 2]),
                 A + (C0 + it * 64 + c) * SS + k * 4);
        }
        cp_commit();
    };

    issue(0, 0);
    issue(1, 1);

    ull acc[2][8];
#pragma unroll
    for (int t = 0; t < 2; t++)
#pragma unroll
        for (int jp = 0; jp < 8; jp++) acc[t][jp] = 0ull;

    for (int it = 0; it < 8; it++) {
        const int buf = it & 1;
        if (it < 7)
            asm volatile("cp.async.wait_group 1;");
        else
            asm volatile("cp.async.wait_group 0;");
        __syncthreads();

        const float* xa = &xs[buf][l * XSROW + w * 8];
        const float* xb = &xs[buf][(32 + l) * XSROW + w * 8];
        const ull* Arow = &As[buf][w * 8 * 8];

#pragma unroll
        for (int cc = 0; cc < 2; cc++) {
            float4 va = *reinterpret_cast<const float4*>(xa + cc * 4);
            float4 vb = *reinterpret_cast<const float4*>(xb + cc * 4);
            float fa[4] = {va.x, va.y, va.z, va.w};
            float fb[4] = {vb.x, vb.y, vb.z, vb.w};
#pragma unroll
            for (int k = 0; k < 4; k++) {
                const int c = cc * 4 + k;
                ull xda = dup2(fa[k]);
                ull xdb = dup2(fb[k]);
#pragma unroll
                for (int jq = 0; jq < 4; jq++) {
                    ulonglong2 a2 = *reinterpret_cast<const ulonglong2*>(
                        Arow + c * 8 + jq * 2);
                    fma2(acc[0][jq * 2], xda, a2.x);
                    fma2(acc[0][jq * 2 + 1], xda, a2.y);
                    fma2(acc[1][jq * 2], xdb, a2.x);
                    fma2(acc[1][jq * 2 + 1], xdb, a2.y);
                }
            }
        }
        __syncthreads();
        if (it + 2 < 8) issue(it + 2, buf);
    }

    // ---- cross-eighth reduce (alias xs as red[8 e][64 t][8 jp] ull) ----
    __syncthreads();
    ull* red = reinterpret_cast<ull*>(&xs[0][0]);
#pragma unroll
    for (int jp = 0; jp < 8; jp++) {
        red[((w * 64) + l) * 8 + jp] = acc[0][jp];
        red[((w * 64) + 32 + l) * 8 + jp] = acc[1][jp];
    }
    __syncthreads();

    const int jj = tid >> 6;  // 0..3 -> states 4jj..4jj+3
    const int t = tid & 63;
    ull s0 = 0ull, s1 = 0ull;
#pragma unroll
    for (int e = 0; e < 8; e++) {
        ulonglong2 v = *reinterpret_cast<const ulonglong2*>(
            &red[(e * 64 + t) * 8 + jj * 2]);
        s0 = add2(s0, v.x);
        s1 = add2(s1, v.y);
    }
    {
        ulonglong2 v;
        v.x = s0;
        v.y = s1;
        *reinterpret_cast<ulonglong2*>(
            &g_xstate[half][(T0 + t) * SS + jj * 4]) = v;
    }

    // chunk sum over 64 tokens
#pragma unroll
    for (int o = 16; o; o >>= 1) {
        s0 = add2(s0, __shfl_xor_sync(0xffffffffu, s0, o));
        s1 = add2(s1, __shfl_xor_sync(0xffffffffu, s1, o));
    }
    if (l == 0) {
        csum_s[w][0] = s0;
        csum_s[w][1] = s1;
    }
    __syncthreads();
    if (tid < 4) {
        ulonglong2 v;
        v.x = add2(csum_s[2 * tid][0], csum_s[2 * tid + 1][0]);
        v.y = add2(csum_s[2 * tid][1], csum_s[2 * tid + 1][1]);
        *reinterpret_cast<ulonglong2*>(
            &g_chsum[half][chunk * SS + tid * 4]) = v;
    }
}

// ================= K2: exclusive scan of chunk sums =================
// Grid = 16 blocks (b x jgroup); 128 threads = one per chunk.
__global__ void __launch_bounds__(128) k2_scan() {
    const int b = blockIdx.x >> 2;
    const int jg = blockIdx.x & 3;
    const int ch = threadIdx.x;
    const long idx = ((long)b * NCHUNK + ch) * SS + jg * 4;

    float4 s0 = *reinterpret_cast<const float4*>(&g_chsum[0][idx]);
    float4 s1 = *reinterpret_cast<const float4*>(&g_chsum[1][idx]);
    float4 s = make_float4(s0.x + s1.x, s0.y + s1.y, s0.z + s1.z, s0.w + s1.w);

    __shared__ float4 sc[NCHUNK];
    sc[ch] = s;
    __syncthreads();
    float4 v = s;
    for (int o = 1; o < NCHUNK; o <<= 1) {
        float4 u = (ch >= o) ? sc[ch - o] : make_float4(0.f, 0.f, 0.f, 0.f);
        __syncthreads();
        v.x += u.x; v.y += u.y; v.z += u.z; v.w += u.w;
        sc[ch] = v;
        __syncthreads();
    }
    float4 e = make_float4(v.x - s.x, v.y - s.y, v.z - s.z, v.w - s.w);
    *reinterpret_cast<float4*>(&g_cprefix[idx]) = e;
}

// ================= K3: local cumsum + (cumstate @ D) =================
// Grid = 1024: block = (64-token chunk) x (512-c half), 256 thr = 8 warps.
// Cumsum recomputed per c-half (cheap, L2 reads). Thread owns 2 channels.
__global__ void __launch_bounds__(256) k3_out(const float* __restrict__ Dg,
                                              float* __restrict__ out) {
    __shared__ ull cs_s[CHUNK][SS + 2];  // duplicated pairs; 144B rows

    const int tid = threadIdx.x;
    const int chunk = blockIdx.x >> 1;
    const int half = blockIdx.x & 1;
    const long T0 = (long)chunk * 64;
    const int w = tid >> 5;
    const int l = tid & 31;

    // Warp w computes cumsum for states j = 2w, 2w+1.
#pragma unroll
    for (int jj = 0; jj < 2; jj++) {
        const int j = w * 2 + jj;
        const float pfx = g_cprefix[chunk * SS + j];
        float v0 = g_xstate[0][(T0 + l) * SS + j] +
                   g_xstate[1][(T0 + l) * SS + j];
        float v1 = g_xstate[0][(T0 + 32 + l) * SS + j] +
                   g_xstate[1][(T0 + 32 + l) * SS + j];
#pragma unroll
        for (int o = 1; o < 32; o <<= 1) {
            float u = __shfl_up_sync(0xffffffffu, v0, o);
            if (l >= o) v0 += u;
        }
        const float carry = __shfl_sync(0xffffffffu, v0, 31);
#pragma unroll
        for (int o = 1; o < 32; o <<= 1) {
            float u = __shfl_up_sync(0xffffffffu, v1, o);
            if (l >= o) v1 += u;
        }
        cs_s[l][j] = dup2(v0 + pfx);
        cs_s[32 + l][j] = dup2(v1 + pfx + carry);
    }
    __syncthreads();

    // D fragment: thread owns c = half*512 + 2*tid (+0,1)
    const int cbase = half * 512 + tid * 2;
    ull dfrag[SS];
#pragma unroll
    for (int j = 0; j < SS; j++)
        dfrag[j] = *reinterpret_cast<const ull*>(Dg + j * CC + cbase);

    float* op = out + T0 * CC + cbase;
#pragma unroll 4
    for (int tt = 0; tt < CHUNK; tt++) {
        ull oa = 0ull, ob = 0ull;
#pragma unroll
        for (int q = 0; q < 8; q++) {
            ulonglong2 c2 =
                *reinterpret_cast<const ulonglong2*>(&cs_s[tt][q * 2]);  // bcast
            fma2(oa, c2.x, dfrag[2 * q]);
            fma2(ob, c2.y, dfrag[2 * q + 1]);
        }
        asm("add.rn.f32x2 %0, %0, %1;" : "+l"(oa) : "l"(ob));
        *reinterpret_cast<ull*>(op + (long)tt * CC) = oa;
    }
}

extern "C" void kernel_launch(void* const* d_in, const int* in_sizes, int n_in,
                              void* d_out, int out_size) {
    const float* x = (const float*)d_in[0];
    const float* A = (const float*)d_in[1];
    const float* D = (const float*)d_in[2];
    float* out = (float*)d_out;

    k1_xstate<<<NCHUNKS_TOT * 2, 256>>>(x, A);
    k2_scan<<<16, 128>>>();
    k3_out<<<NCHUNKS_TOT * 2, 256>>>(D, out);
}